// round 11
// baseline (speedup 1.0000x reference)
#include <cuda_runtime.h>
#include <cuda_fp16.h>
#include <cstdint>

#define MAX_N 100352
#define MAX_E 1700000
#define MAX_PART 512
#define DIM 128

// ---------------- small device-global scratch (~8.4 MB) ----------------
__device__ int   g_deg[MAX_N];        // degree, then CSR fill cursor
__device__ float g_dinv[MAX_N];
__device__ float g_invcnt[MAX_N];
__device__ int   g_row[MAX_N + 1];
__device__ int   g_col[MAX_E];
__device__ int   g_part[MAX_PART];
__device__ int   g_idx64;

// ---------------- edge-index dtype detection ----------------
__global__ void detect_kernel(const int* ei32, long long words) {
    __shared__ int s;
    if (threadIdx.x == 0) s = 1;
    __syncthreads();
    long long limit = words < 8192 ? words : 8192;
    for (long long j = 1 + 2LL * threadIdx.x; j < limit; j += 2LL * blockDim.x)
        if (ei32[j] != 0) s = 0;
    __syncthreads();
    if (threadIdx.x == 0 && words > 0) g_idx64 = s;
}

__device__ __forceinline__ void load_edge(const void* ei, long long E, long long e,
                                          int& src, int& dst) {
    if (g_idx64) {
        const long long* p = (const long long*)ei;
        src = (int)p[e]; dst = (int)p[E + e];
    } else {
        const int* p = (const int*)ei;
        src = p[e]; dst = p[E + e];
    }
}

// ---------------- feat fp32 -> fp16 (slot high half of d_out); zero g_deg ----------------
__global__ __launch_bounds__(256) void conv_kernel(
    const float* __restrict__ feat, float* __restrict__ out, int n)
{
    int total = n * 32;
    for (int idx = blockIdx.x * 256 + threadIdx.x; idx < total; idx += gridDim.x * 256) {
        int row = idx >> 5, q = idx & 31;
        float4 v = ((const float4*)feat)[idx];
        __half2* dst = (__half2*)((__half*)(out + (size_t)row * DIM + 64)) + q * 2;
        dst[0] = __floats2half2_rn(v.x, v.y);
        dst[1] = __floats2half2_rn(v.z, v.w);
    }
    for (int i = blockIdx.x * 256 + threadIdx.x; i < n; i += gridDim.x * 256)
        g_deg[i] = 0;
}

// ---------------- degree count ----------------
__global__ void count_deg_kernel(const void* ei, long long E) {
    long long e = (long long)blockIdx.x * blockDim.x + threadIdx.x;
    if (e < E) {
        int s, d; load_edge(ei, E, e, s, d);
        atomicAdd(&g_deg[d], 1);
    }
}

// ---------------- precompute norms + scan partials (fused) ----------------
__global__ __launch_bounds__(256) void precomp_partial_kernel(int n) {
    __shared__ int red[256];
    int i = blockIdx.x * 256 + threadIdx.x;
    int d = 0;
    if (i < n) {
        d = g_deg[i];
        g_dinv[i]   = rsqrtf((float)d + 1.0f);
        g_invcnt[i] = 1.0f / (float)(d > 0 ? d : 1);
    }
    red[threadIdx.x] = d;
    __syncthreads();
    for (int s = 128; s > 0; s >>= 1) {
        if (threadIdx.x < s) red[threadIdx.x] += red[threadIdx.x + s];
        __syncthreads();
    }
    if (threadIdx.x == 0) g_part[blockIdx.x] = red[0];
}

__global__ __launch_bounds__(512) void scan_part_kernel(int nb, int n) {
    __shared__ int sp[512];
    int t = threadIdx.x;
    int v = (t < nb) ? g_part[t] : 0;
    sp[t] = v;
    __syncthreads();
    for (int d = 1; d < 512; d <<= 1) {
        int u = (t >= d) ? sp[t - d] : 0;
        __syncthreads();
        sp[t] += u;
        __syncthreads();
    }
    if (t < nb) g_part[t] = sp[t] - v;
    if (t == 511) g_row[n] = sp[511];
}

__global__ __launch_bounds__(256) void rowptr_kernel(int n) {
    __shared__ int sp[256];
    int t = threadIdx.x;
    int i = blockIdx.x * 256 + t;
    int v = (i < n) ? g_deg[i] : 0;
    sp[t] = v;
    __syncthreads();
    for (int d = 1; d < 256; d <<= 1) {
        int u = (t >= d) ? sp[t - d] : 0;
        __syncthreads();
        sp[t] += u;
        __syncthreads();
    }
    int excl = sp[t] - v + g_part[blockIdx.x];
    if (i < n) { g_row[i] = excl; g_deg[i] = excl; }
}

__global__ void fill_kernel(const void* ei, long long E) {
    long long e = (long long)blockIdx.x * blockDim.x + threadIdx.x;
    if (e < E) {
        int s, d; load_edge(ei, E, e, s, d);
        int pos = atomicAdd(&g_deg[d], 1);
        g_col[pos] = s;
    }
}

// ---------------- L1 aggregate: latency-optimized gather ----------------
// warp per node. Indices + dinv prefetched cooperatively (32 at a time) and
// broadcast via shfl; row loads unrolled x4 for MLP. Reads slot-high bytes,
// writes slot-low bytes -> disjoint, race-free.
__global__ __launch_bounds__(256) void agg1_kernel(float* __restrict__ out, int n) {
    int node = blockIdx.x * 8 + (threadIdx.x >> 5);
    if (node >= n) return;
    const int lane = threadIdx.x & 31;
    const float di = g_dinv[node];

    const __half2* selfp = (const __half2*)((const __half*)(out + (size_t)node * DIM + 64)) + lane * 2;
    float2 f0 = __half22float2(selfp[0]);
    float2 f1 = __half22float2(selfp[1]);
    float c0 = di * di;
    float4 acc = make_float4(c0 * f0.x, c0 * f0.y, c0 * f1.x, c0 * f1.y);

    const int p0 = g_row[node];
    const int pend = g_row[node + 1];

    for (int base = p0; base < pend; base += 32) {
        const int cnt = min(32, pend - base);
        int jl = 0; float dl = 0.f;
        if (lane < cnt) {
            jl = g_col[base + lane];
            dl = g_dinv[jl];
        }
        int k = 0;
        for (; k + 4 <= cnt; k += 4) {
            int j0 = __shfl_sync(0xffffffffu, jl, k);
            int j1 = __shfl_sync(0xffffffffu, jl, k + 1);
            int j2 = __shfl_sync(0xffffffffu, jl, k + 2);
            int j3 = __shfl_sync(0xffffffffu, jl, k + 3);
            float ca = di * __shfl_sync(0xffffffffu, dl, k);
            float cb = di * __shfl_sync(0xffffffffu, dl, k + 1);
            float cc = di * __shfl_sync(0xffffffffu, dl, k + 2);
            float cd = di * __shfl_sync(0xffffffffu, dl, k + 3);
            const __half2* v0 = (const __half2*)((const __half*)(out + (size_t)j0 * DIM + 64)) + lane * 2;
            const __half2* v1 = (const __half2*)((const __half*)(out + (size_t)j1 * DIM + 64)) + lane * 2;
            const __half2* v2 = (const __half2*)((const __half*)(out + (size_t)j2 * DIM + 64)) + lane * 2;
            const __half2* v3 = (const __half2*)((const __half*)(out + (size_t)j3 * DIM + 64)) + lane * 2;
            __half2 a0 = v0[0], a1 = v0[1];
            __half2 b0 = v1[0], b1 = v1[1];
            __half2 e0 = v2[0], e1 = v2[1];
            __half2 d0 = v3[0], d1 = v3[1];
            float2 x;
            x = __half22float2(a0); acc.x += ca * x.x; acc.y += ca * x.y;
            x = __half22float2(a1); acc.z += ca * x.x; acc.w += ca * x.y;
            x = __half22float2(b0); acc.x += cb * x.x; acc.y += cb * x.y;
            x = __half22float2(b1); acc.z += cb * x.x; acc.w += cb * x.y;
            x = __half22float2(e0); acc.x += cc * x.x; acc.y += cc * x.y;
            x = __half22float2(e1); acc.z += cc * x.x; acc.w += cc * x.y;
            x = __half22float2(d0); acc.x += cd * x.x; acc.y += cd * x.y;
            x = __half22float2(d1); acc.z += cd * x.x; acc.w += cd * x.y;
        }
        for (; k < cnt; k++) {
            int j = __shfl_sync(0xffffffffu, jl, k);
            float c = di * __shfl_sync(0xffffffffu, dl, k);
            const __half2* v = (const __half2*)((const __half*)(out + (size_t)j * DIM + 64)) + lane * 2;
            float2 fa = __half22float2(v[0]), fb = __half22float2(v[1]);
            acc.x += c * fa.x; acc.y += c * fa.y; acc.z += c * fb.x; acc.w += c * fb.y;
        }
    }
    __half2* dst = (__half2*)(out + (size_t)node * DIM) + lane * 2;
    dst[0] = __floats2half2_rn(acc.x, acc.y);
    dst[1] = __floats2half2_rn(acc.z, acc.w);
}

// ---------------- tensor-core mma helper ----------------
__device__ __forceinline__ void mma16816(float* c, uint32_t a0, uint32_t a1,
                                         uint32_t a2, uint32_t a3,
                                         uint32_t b0, uint32_t b1) {
    asm volatile(
        "mma.sync.aligned.m16n8k16.row.col.f32.f16.f16.f32 "
        "{%0,%1,%2,%3}, {%4,%5,%6,%7}, {%8,%9}, {%0,%1,%2,%3};"
        : "+f"(c[0]), "+f"(c[1]), "+f"(c[2]), "+f"(c[3])
        : "r"(a0), "r"(a1), "r"(a2), "r"(a3), "r"(b0), "r"(b1));
}

// ---------------- GEMM1 (tc): X = relu(agg@W1^T + b1) -> fp16 slot low ----------------
__global__ __launch_bounds__(256) void mma_gemm1(
    const float* __restrict__ W1, const float* __restrict__ b1,
    float* __restrict__ out, int n)
{
    const int KP = 136;
    extern __shared__ __half sh[];
    __half* As = sh;
    __half* Bs = sh + 128 * KP;
    float* bias_s = (float*)(Bs + 128 * KP);
    const int tid = threadIdx.x;
    const int block_row = blockIdx.x * 128;

    for (int i = tid; i < 128 * 32; i += 256) {
        int r = i >> 5, q = i & 31;
        float4 w = ((const float4*)W1)[i];
        __half2* dst = (__half2*)&Bs[r * KP + q * 4];
        dst[0] = __floats2half2_rn(w.x, w.y);
        dst[1] = __floats2half2_rn(w.z, w.w);
    }
    for (int i = tid; i < 128 * 16; i += 256) {
        int r = i >> 4, q = i & 15;
        int gr = block_row + r;
        uint4 v = make_uint4(0, 0, 0, 0);
        if (gr < n) v = ((const uint4*)(out + (size_t)gr * DIM))[q];
        *(uint4*)&As[r * KP + q * 8] = v;
    }
    if (tid < 128) bias_s[tid] = b1[tid];
    __syncthreads();

    const int warp = tid >> 5, lane = tid & 31;
    const int m0 = warp * 16;
    const int r = lane >> 2, c2 = (lane & 3) * 2;

    float acc[16][4];
    #pragma unroll
    for (int t = 0; t < 16; t++)
        #pragma unroll
        for (int q = 0; q < 4; q++) acc[t][q] = 0.f;

    #pragma unroll
    for (int kk = 0; kk < 128; kk += 16) {
        uint32_t a0 = *(const uint32_t*)&As[(m0 + r) * KP + kk + c2];
        uint32_t a1 = *(const uint32_t*)&As[(m0 + r + 8) * KP + kk + c2];
        uint32_t a2 = *(const uint32_t*)&As[(m0 + r) * KP + kk + 8 + c2];
        uint32_t a3 = *(const uint32_t*)&As[(m0 + r + 8) * KP + kk + 8 + c2];
        #pragma unroll
        for (int nt = 0; nt < 16; nt++) {
            uint32_t b0 = *(const uint32_t*)&Bs[(nt * 8 + r) * KP + kk + c2];
            uint32_t b1r = *(const uint32_t*)&Bs[(nt * 8 + r) * KP + kk + 8 + c2];
            mma16816(acc[nt], a0, a1, a2, a3, b0, b1r);
        }
    }

    const int row0 = block_row + m0 + r;
    #pragma unroll
    for (int nt = 0; nt < 16; nt++) {
        int col = nt * 8 + c2;
        float bx = bias_s[col], by = bias_s[col + 1];
        if (row0 < n) {
            __half2 h = __floats2half2_rn(fmaxf(acc[nt][0] + bx, 0.f),
                                          fmaxf(acc[nt][1] + by, 0.f));
            *(__half2*)((__half*)(out + (size_t)row0 * DIM) + col) = h;
        }
        if (row0 + 8 < n) {
            __half2 h = __floats2half2_rn(fmaxf(acc[nt][2] + bx, 0.f),
                                          fmaxf(acc[nt][3] + by, 0.f));
            *(__half2*)((__half*)(out + (size_t)(row0 + 8) * DIM) + col) = h;
        }
    }
}

// ---------------- SAGE sum: latency-optimized gather -> fp16 slot high ----------------
__global__ __launch_bounds__(256) void sgather_kernel(float* __restrict__ out, int n) {
    int node = blockIdx.x * 8 + (threadIdx.x >> 5);
    if (node >= n) return;
    const int lane = threadIdx.x & 31;

    float4 acc = make_float4(0.f, 0.f, 0.f, 0.f);
    const int p0 = g_row[node];
    const int pend = g_row[node + 1];

    for (int base = p0; base < pend; base += 32) {
        const int cnt = min(32, pend - base);
        int jl = 0;
        if (lane < cnt) jl = g_col[base + lane];
        int k = 0;
        for (; k + 4 <= cnt; k += 4) {
            int j0 = __shfl_sync(0xffffffffu, jl, k);
            int j1 = __shfl_sync(0xffffffffu, jl, k + 1);
            int j2 = __shfl_sync(0xffffffffu, jl, k + 2);
            int j3 = __shfl_sync(0xffffffffu, jl, k + 3);
            const __half2* v0 = (const __half2*)(out + (size_t)j0 * DIM) + lane * 2;
            const __half2* v1 = (const __half2*)(out + (size_t)j1 * DIM) + lane * 2;
            const __half2* v2 = (const __half2*)(out + (size_t)j2 * DIM) + lane * 2;
            const __half2* v3 = (const __half2*)(out + (size_t)j3 * DIM) + lane * 2;
            __half2 a0 = v0[0], a1 = v0[1];
            __half2 b0 = v1[0], b1 = v1[1];
            __half2 e0 = v2[0], e1 = v2[1];
            __half2 d0 = v3[0], d1 = v3[1];
            float2 x;
            x = __half22float2(a0); acc.x += x.x; acc.y += x.y;
            x = __half22float2(a1); acc.z += x.x; acc.w += x.y;
            x = __half22float2(b0); acc.x += x.x; acc.y += x.y;
            x = __half22float2(b1); acc.z += x.x; acc.w += x.y;
            x = __half22float2(e0); acc.x += x.x; acc.y += x.y;
            x = __half22float2(e1); acc.z += x.x; acc.w += x.y;
            x = __half22float2(d0); acc.x += x.x; acc.y += x.y;
            x = __half22float2(d1); acc.z += x.x; acc.w += x.y;
        }
        for (; k < cnt; k++) {
            int j = __shfl_sync(0xffffffffu, jl, k);
            const __half2* v = (const __half2*)(out + (size_t)j * DIM) + lane * 2;
            float2 fa = __half22float2(v[0]), fb = __half22float2(v[1]);
            acc.x += fa.x; acc.y += fa.y; acc.z += fb.x; acc.w += fb.y;
        }
    }
    __half2* shp = (__half2*)((__half*)(out + (size_t)node * DIM + 64)) + lane * 2;
    shp[0] = __floats2half2_rn(acc.x, acc.y);
    shp[1] = __floats2half2_rn(acc.z, acc.w);
}

// ---------------- GEMM2 (tc): out = relu([S*invcnt | X] @ [Wl|Wr]^T + bl) ----------------
__global__ __launch_bounds__(256) void mma_gemm2(
    const float* __restrict__ Wl, const float* __restrict__ bl,
    const float* __restrict__ Wr, float* __restrict__ out, int n)
{
    const int KP = 264;
    extern __shared__ __half sh[];
    __half* As = sh;
    __half* Bs = sh + 128 * KP;
    float* bias_s = (float*)(Bs + 128 * KP);
    const int tid = threadIdx.x;
    const int block_row = blockIdx.x * 128;

    for (int i = tid; i < 128 * 32; i += 256) {
        int r = i >> 5, q = i & 31;
        float4 w = ((const float4*)Wl)[i];
        __half2* dst = (__half2*)&Bs[r * KP + q * 4];
        dst[0] = __floats2half2_rn(w.x, w.y);
        dst[1] = __floats2half2_rn(w.z, w.w);
    }
    for (int i = tid; i < 128 * 32; i += 256) {
        int r = i >> 5, q = i & 31;
        float4 w = ((const float4*)Wr)[i];
        __half2* dst = (__half2*)&Bs[r * KP + 128 + q * 4];
        dst[0] = __floats2half2_rn(w.x, w.y);
        dst[1] = __floats2half2_rn(w.z, w.w);
    }
    for (int i = tid; i < 128 * 64; i += 256) {
        int row = i >> 6, q = i & 63;
        int gr = block_row + row;
        __half2 xh = __float2half2_rn(0.f), shv = __float2half2_rn(0.f);
        if (gr < n) {
            const __half2* slot = (const __half2*)(out + (size_t)gr * DIM);
            xh = slot[q];
            __half2 sr = slot[64 + q];
            float ic = g_invcnt[gr];
            float2 sf = __half22float2(sr);
            shv = __floats2half2_rn(sf.x * ic, sf.y * ic);
        }
        ((__half2*)&As[row * KP])[q] = shv;
        ((__half2*)&As[row * KP + 128])[q] = xh;
    }
    if (tid < 128) bias_s[tid] = bl[tid];
    __syncthreads();

    const int warp = tid >> 5, lane = tid & 31;
    const int m0 = warp * 16;
    const int r = lane >> 2, c2 = (lane & 3) * 2;

    float acc[16][4];
    #pragma unroll
    for (int t = 0; t < 16; t++)
        #pragma unroll
        for (int q = 0; q < 4; q++) acc[t][q] = 0.f;

    #pragma unroll
    for (int kk = 0; kk < 256; kk += 16) {
        uint32_t a0 = *(const uint32_t*)&As[(m0 + r) * KP + kk + c2];
        uint32_t a1 = *(const uint32_t*)&As[(m0 + r + 8) * KP + kk + c2];
        uint32_t a2 = *(const uint32_t*)&As[(m0 + r) * KP + kk + 8 + c2];
        uint32_t a3 = *(const uint32_t*)&As[(m0 + r + 8) * KP + kk + 8 + c2];
        #pragma unroll
        for (int nt = 0; nt < 16; nt++) {
            uint32_t b0 = *(const uint32_t*)&Bs[(nt * 8 + r) * KP + kk + c2];
            uint32_t b1r = *(const uint32_t*)&Bs[(nt * 8 + r) * KP + kk + 8 + c2];
            mma16816(acc[nt], a0, a1, a2, a3, b0, b1r);
        }
    }

    const int row0 = block_row + m0 + r;
    #pragma unroll
    for (int nt = 0; nt < 16; nt++) {
        int col = nt * 8 + c2;
        float bx = bias_s[col], by = bias_s[col + 1];
        if (row0 < n) {
            float2 o = make_float2(fmaxf(acc[nt][0] + bx, 0.f),
                                   fmaxf(acc[nt][1] + by, 0.f));
            *(float2*)(out + (size_t)row0 * DIM + col) = o;
        }
        if (row0 + 8 < n) {
            float2 o = make_float2(fmaxf(acc[nt][2] + bx, 0.f),
                                   fmaxf(acc[nt][3] + by, 0.f));
            *(float2*)(out + (size_t)(row0 + 8) * DIM + col) = o;
        }
    }
}

static const int SMEM_G1 = (128 * 136 * 2) * 2 + 512;
static const int SMEM_G2 = (128 * 264 * 2) * 2 + 512;

// ---------------- host launcher ----------------
extern "C" void kernel_launch(void* const* d_in, const int* in_sizes, int n_in,
                              void* d_out, int out_size) {
    const float* feat = (const float*)d_in[0];
    const void*  ei   = d_in[1];
    const float* W1   = (const float*)d_in[2];
    const float* b1   = (const float*)d_in[3];
    const float* Wl   = (const float*)d_in[4];
    const float* bl   = (const float*)d_in[5];
    const float* Wr   = (const float*)d_in[6];
    float* out = (float*)d_out;

    const int n = in_sizes[0] / DIM;
    const long long E = (long long)in_sizes[1] / 2;

    static bool attr_done = false;
    if (!attr_done) {
        cudaFuncSetAttribute(mma_gemm1, cudaFuncAttributeMaxDynamicSharedMemorySize, SMEM_G1);
        cudaFuncSetAttribute(mma_gemm2, cudaFuncAttributeMaxDynamicSharedMemorySize, SMEM_G2);
        attr_done = true;
    }

    const int eb = (int)((E + 255) / 256);
    const int nb = (n + 255) / 256;
    const int wb = (n + 7) / 8;
    const int mb = (n + 127) / 128;
    const int cb = (n * 32 + 255) / 256;

    detect_kernel<<<1, 256>>>((const int*)ei, 2 * E);
    conv_kernel<<<cb, 256>>>(feat, out, n);
    count_deg_kernel<<<eb, 256>>>(ei, E);
    precomp_partial_kernel<<<nb, 256>>>(n);
    scan_part_kernel<<<1, 512>>>(nb, n);
    rowptr_kernel<<<nb, 256>>>(n);
    fill_kernel<<<eb, 256>>>(ei, E);
    agg1_kernel<<<wb, 256>>>(out, n);
    mma_gemm1<<<mb, 256, SMEM_G1>>>(W1, b1, out, n);
    sgather_kernel<<<wb, 256>>>(out, n);
    mma_gemm2<<<mb, 256, SMEM_G2>>>(Wl, bl, Wr, out, n);
}

// round 12
// speedup vs baseline: 1.0613x; 1.0613x over previous
#include <cuda_runtime.h>
#include <cuda_fp16.h>
#include <cstdint>

#define MAX_N 100352
#define MAX_E 1700000
#define MAX_PART 512
#define DIM 128

// ---------------- small device-global scratch (~8.4 MB) ----------------
__device__ int   g_deg[MAX_N];        // degree, then CSR fill cursor
__device__ float g_dinv[MAX_N];
__device__ float g_invcnt[MAX_N];
__device__ int   g_row[MAX_N + 1];
__device__ int   g_col[MAX_E];
__device__ int   g_part[MAX_PART];
__device__ int   g_idx64;

// ---------------- edge-index dtype detection ----------------
__global__ void detect_kernel(const int* ei32, long long words) {
    __shared__ int s;
    if (threadIdx.x == 0) s = 1;
    __syncthreads();
    long long limit = words < 8192 ? words : 8192;
    for (long long j = 1 + 2LL * threadIdx.x; j < limit; j += 2LL * blockDim.x)
        if (ei32[j] != 0) s = 0;
    __syncthreads();
    if (threadIdx.x == 0 && words > 0) g_idx64 = s;
}

__device__ __forceinline__ void load_edge(const void* ei, long long E, long long e,
                                          int& src, int& dst) {
    if (g_idx64) {
        const long long* p = (const long long*)ei;
        src = (int)p[e]; dst = (int)p[E + e];
    } else {
        const int* p = (const int*)ei;
        src = p[e]; dst = p[E + e];
    }
}

// ---------------- feat fp32 -> fp16 (slot high half of d_out); zero g_deg ----------------
__global__ __launch_bounds__(256) void conv_kernel(
    const float* __restrict__ feat, float* __restrict__ out, int n)
{
    int total = n * 32;
    for (int idx = blockIdx.x * 256 + threadIdx.x; idx < total; idx += gridDim.x * 256) {
        int row = idx >> 5, q = idx & 31;
        float4 v = ((const float4*)feat)[idx];
        __half2* dst = (__half2*)((__half*)(out + (size_t)row * DIM + 64)) + q * 2;
        dst[0] = __floats2half2_rn(v.x, v.y);
        dst[1] = __floats2half2_rn(v.z, v.w);
    }
    for (int i = blockIdx.x * 256 + threadIdx.x; i < n; i += gridDim.x * 256)
        g_deg[i] = 0;
}

// ---------------- degree count ----------------
__global__ void count_deg_kernel(const void* ei, long long E) {
    long long e = (long long)blockIdx.x * blockDim.x + threadIdx.x;
    if (e < E) {
        int s, d; load_edge(ei, E, e, s, d);
        atomicAdd(&g_deg[d], 1);
    }
}

// ---------------- precompute norms + scan partials (fused) ----------------
__global__ __launch_bounds__(256) void precomp_partial_kernel(int n) {
    __shared__ int red[256];
    int i = blockIdx.x * 256 + threadIdx.x;
    int d = 0;
    if (i < n) {
        d = g_deg[i];
        g_dinv[i]   = rsqrtf((float)d + 1.0f);
        g_invcnt[i] = 1.0f / (float)(d > 0 ? d : 1);
    }
    red[threadIdx.x] = d;
    __syncthreads();
    for (int s = 128; s > 0; s >>= 1) {
        if (threadIdx.x < s) red[threadIdx.x] += red[threadIdx.x + s];
        __syncthreads();
    }
    if (threadIdx.x == 0) g_part[blockIdx.x] = red[0];
}

__global__ __launch_bounds__(512) void scan_part_kernel(int nb, int n) {
    __shared__ int sp[512];
    int t = threadIdx.x;
    int v = (t < nb) ? g_part[t] : 0;
    sp[t] = v;
    __syncthreads();
    for (int d = 1; d < 512; d <<= 1) {
        int u = (t >= d) ? sp[t - d] : 0;
        __syncthreads();
        sp[t] += u;
        __syncthreads();
    }
    if (t < nb) g_part[t] = sp[t] - v;
    if (t == 511) g_row[n] = sp[511];
}

__global__ __launch_bounds__(256) void rowptr_kernel(int n) {
    __shared__ int sp[256];
    int t = threadIdx.x;
    int i = blockIdx.x * 256 + t;
    int v = (i < n) ? g_deg[i] : 0;
    sp[t] = v;
    __syncthreads();
    for (int d = 1; d < 256; d <<= 1) {
        int u = (t >= d) ? sp[t - d] : 0;
        __syncthreads();
        sp[t] += u;
        __syncthreads();
    }
    int excl = sp[t] - v + g_part[blockIdx.x];
    if (i < n) { g_row[i] = excl; g_deg[i] = excl; }
}

__global__ void fill_kernel(const void* ei, long long E) {
    long long e = (long long)blockIdx.x * blockDim.x + threadIdx.x;
    if (e < E) {
        int s, d; load_edge(ei, E, e, s, d);
        int pos = atomicAdd(&g_deg[d], 1);
        g_col[pos] = s;
    }
}

// ---------------- L1 aggregate: half-warp-per-neighbor, LDG.128 gather ----------------
// warp per node; lanes 0-15 take neighbor p, lanes 16-31 take p+1. Each lane
// loads 16B (8 halves) of the 256B fp16 row. 8 fp32 accumulators per lane;
// shfl_xor(16) combine; half 0 stores. Reads slot-high, writes slot-low.
__global__ __launch_bounds__(256) void agg1_kernel(float* __restrict__ out, int n) {
    int node = blockIdx.x * 8 + (threadIdx.x >> 5);
    if (node >= n) return;
    const int lane = threadIdx.x & 31;
    const int half = lane >> 4, sub = lane & 15;
    const float di = g_dinv[node];

    float acc[8];
    {
        uint4 v = *(const uint4*)((const __half*)(out + (size_t)node * DIM + 64) + sub * 8);
        const __half2* h = (const __half2*)&v;
        float c0 = (half == 0) ? di * di : 0.f;
        #pragma unroll
        for (int q = 0; q < 4; q++) {
            float2 f = __half22float2(h[q]);
            acc[2 * q] = c0 * f.x; acc[2 * q + 1] = c0 * f.y;
        }
    }

    const int p0 = g_row[node], pend = g_row[node + 1];
    int p = p0;
    #pragma unroll 2
    for (; p + 2 <= pend; p += 2) {
        int j = g_col[p + half];
        float c = di * g_dinv[j];
        uint4 v = *(const uint4*)((const __half*)(out + (size_t)j * DIM + 64) + sub * 8);
        const __half2* h = (const __half2*)&v;
        #pragma unroll
        for (int q = 0; q < 4; q++) {
            float2 f = __half22float2(h[q]);
            acc[2 * q] += c * f.x; acc[2 * q + 1] += c * f.y;
        }
    }
    if (p + half < pend) {
        int j = g_col[p + half];
        float c = di * g_dinv[j];
        uint4 v = *(const uint4*)((const __half*)(out + (size_t)j * DIM + 64) + sub * 8);
        const __half2* h = (const __half2*)&v;
        #pragma unroll
        for (int q = 0; q < 4; q++) {
            float2 f = __half22float2(h[q]);
            acc[2 * q] += c * f.x; acc[2 * q + 1] += c * f.y;
        }
    }

    #pragma unroll
    for (int q = 0; q < 8; q++)
        acc[q] += __shfl_xor_sync(0xffffffffu, acc[q], 16);

    if (half == 0) {
        __half2 hh[4];
        #pragma unroll
        for (int q = 0; q < 4; q++) hh[q] = __floats2half2_rn(acc[2 * q], acc[2 * q + 1]);
        *(uint4*)((__half*)(out + (size_t)node * DIM) + sub * 8) = *(const uint4*)hh;
    }
}

// ---------------- tensor-core mma helper ----------------
__device__ __forceinline__ void mma16816(float* c, uint32_t a0, uint32_t a1,
                                         uint32_t a2, uint32_t a3,
                                         uint32_t b0, uint32_t b1) {
    asm volatile(
        "mma.sync.aligned.m16n8k16.row.col.f32.f16.f16.f32 "
        "{%0,%1,%2,%3}, {%4,%5,%6,%7}, {%8,%9}, {%0,%1,%2,%3};"
        : "+f"(c[0]), "+f"(c[1]), "+f"(c[2]), "+f"(c[3])
        : "r"(a0), "r"(a1), "r"(a2), "r"(a3), "r"(b0), "r"(b1));
}

// ---------------- GEMM1 (tc): X = relu(agg@W1^T + b1) -> fp16 slot low ----------------
__global__ __launch_bounds__(256) void mma_gemm1(
    const float* __restrict__ W1, const float* __restrict__ b1,
    float* __restrict__ out, int n)
{
    const int KP = 136;
    extern __shared__ __half sh[];
    __half* As = sh;
    __half* Bs = sh + 128 * KP;
    float* bias_s = (float*)(Bs + 128 * KP);
    const int tid = threadIdx.x;
    const int block_row = blockIdx.x * 128;

    for (int i = tid; i < 128 * 32; i += 256) {
        int r = i >> 5, q = i & 31;
        float4 w = ((const float4*)W1)[i];
        __half2* dst = (__half2*)&Bs[r * KP + q * 4];
        dst[0] = __floats2half2_rn(w.x, w.y);
        dst[1] = __floats2half2_rn(w.z, w.w);
    }
    for (int i = tid; i < 128 * 16; i += 256) {
        int r = i >> 4, q = i & 15;
        int gr = block_row + r;
        uint4 v = make_uint4(0, 0, 0, 0);
        if (gr < n) v = ((const uint4*)(out + (size_t)gr * DIM))[q];
        *(uint4*)&As[r * KP + q * 8] = v;
    }
    if (tid < 128) bias_s[tid] = b1[tid];
    __syncthreads();

    const int warp = tid >> 5, lane = tid & 31;
    const int m0 = warp * 16;
    const int r = lane >> 2, c2 = (lane & 3) * 2;

    float acc[16][4];
    #pragma unroll
    for (int t = 0; t < 16; t++)
        #pragma unroll
        for (int q = 0; q < 4; q++) acc[t][q] = 0.f;

    #pragma unroll
    for (int kk = 0; kk < 128; kk += 16) {
        uint32_t a0 = *(const uint32_t*)&As[(m0 + r) * KP + kk + c2];
        uint32_t a1 = *(const uint32_t*)&As[(m0 + r + 8) * KP + kk + c2];
        uint32_t a2 = *(const uint32_t*)&As[(m0 + r) * KP + kk + 8 + c2];
        uint32_t a3 = *(const uint32_t*)&As[(m0 + r + 8) * KP + kk + 8 + c2];
        #pragma unroll
        for (int nt = 0; nt < 16; nt++) {
            uint32_t b0 = *(const uint32_t*)&Bs[(nt * 8 + r) * KP + kk + c2];
            uint32_t b1r = *(const uint32_t*)&Bs[(nt * 8 + r) * KP + kk + 8 + c2];
            mma16816(acc[nt], a0, a1, a2, a3, b0, b1r);
        }
    }

    const int row0 = block_row + m0 + r;
    #pragma unroll
    for (int nt = 0; nt < 16; nt++) {
        int col = nt * 8 + c2;
        float bx = bias_s[col], by = bias_s[col + 1];
        if (row0 < n) {
            __half2 h = __floats2half2_rn(fmaxf(acc[nt][0] + bx, 0.f),
                                          fmaxf(acc[nt][1] + by, 0.f));
            *(__half2*)((__half*)(out + (size_t)row0 * DIM) + col) = h;
        }
        if (row0 + 8 < n) {
            __half2 h = __floats2half2_rn(fmaxf(acc[nt][2] + bx, 0.f),
                                          fmaxf(acc[nt][3] + by, 0.f));
            *(__half2*)((__half*)(out + (size_t)(row0 + 8) * DIM) + col) = h;
        }
    }
}

// ---------------- SAGE sum: half-warp-per-neighbor LDG.128 gather -> fp16 slot high ----------------
__global__ __launch_bounds__(256) void sgather_kernel(float* __restrict__ out, int n) {
    int node = blockIdx.x * 8 + (threadIdx.x >> 5);
    if (node >= n) return;
    const int lane = threadIdx.x & 31;
    const int half = lane >> 4, sub = lane & 15;

    float acc[8];
    #pragma unroll
    for (int q = 0; q < 8; q++) acc[q] = 0.f;

    const int p0 = g_row[node], pend = g_row[node + 1];
    int p = p0;
    #pragma unroll 2
    for (; p + 2 <= pend; p += 2) {
        int j = g_col[p + half];
        uint4 v = *(const uint4*)((const __half*)(out + (size_t)j * DIM) + sub * 8);
        const __half2* h = (const __half2*)&v;
        #pragma unroll
        for (int q = 0; q < 4; q++) {
            float2 f = __half22float2(h[q]);
            acc[2 * q] += f.x; acc[2 * q + 1] += f.y;
        }
    }
    if (p + half < pend) {
        int j = g_col[p + half];
        uint4 v = *(const uint4*)((const __half*)(out + (size_t)j * DIM) + sub * 8);
        const __half2* h = (const __half2*)&v;
        #pragma unroll
        for (int q = 0; q < 4; q++) {
            float2 f = __half22float2(h[q]);
            acc[2 * q] += f.x; acc[2 * q + 1] += f.y;
        }
    }

    #pragma unroll
    for (int q = 0; q < 8; q++)
        acc[q] += __shfl_xor_sync(0xffffffffu, acc[q], 16);

    if (half == 0) {
        __half2 hh[4];
        #pragma unroll
        for (int q = 0; q < 4; q++) hh[q] = __floats2half2_rn(acc[2 * q], acc[2 * q + 1]);
        *(uint4*)((__half*)(out + (size_t)node * DIM + 64) + sub * 8) = *(const uint4*)hh;
    }
}

// ---------------- GEMM2 (tc): out = relu([S*invcnt | X] @ [Wl|Wr]^T + bl) ----------------
__global__ __launch_bounds__(256) void mma_gemm2(
    const float* __restrict__ Wl, const float* __restrict__ bl,
    const float* __restrict__ Wr, float* __restrict__ out, int n)
{
    const int KP = 264;
    extern __shared__ __half sh[];
    __half* As = sh;
    __half* Bs = sh + 128 * KP;
    float* bias_s = (float*)(Bs + 128 * KP);
    const int tid = threadIdx.x;
    const int block_row = blockIdx.x * 128;

    for (int i = tid; i < 128 * 32; i += 256) {
        int r = i >> 5, q = i & 31;
        float4 w = ((const float4*)Wl)[i];
        __half2* dst = (__half2*)&Bs[r * KP + q * 4];
        dst[0] = __floats2half2_rn(w.x, w.y);
        dst[1] = __floats2half2_rn(w.z, w.w);
    }
    for (int i = tid; i < 128 * 32; i += 256) {
        int r = i >> 5, q = i & 31;
        float4 w = ((const float4*)Wr)[i];
        __half2* dst = (__half2*)&Bs[r * KP + 128 + q * 4];
        dst[0] = __floats2half2_rn(w.x, w.y);
        dst[1] = __floats2half2_rn(w.z, w.w);
    }
    for (int i = tid; i < 128 * 64; i += 256) {
        int row = i >> 6, q = i & 63;
        int gr = block_row + row;
        __half2 xh = __float2half2_rn(0.f), shv = __float2half2_rn(0.f);
        if (gr < n) {
            const __half2* slot = (const __half2*)(out + (size_t)gr * DIM);
            xh = slot[q];
            __half2 sr = slot[64 + q];
            float ic = g_invcnt[gr];
            float2 sf = __half22float2(sr);
            shv = __floats2half2_rn(sf.x * ic, sf.y * ic);
        }
        ((__half2*)&As[row * KP])[q] = shv;
        ((__half2*)&As[row * KP + 128])[q] = xh;
    }
    if (tid < 128) bias_s[tid] = bl[tid];
    __syncthreads();

    const int warp = tid >> 5, lane = tid & 31;
    const int m0 = warp * 16;
    const int r = lane >> 2, c2 = (lane & 3) * 2;

    float acc[16][4];
    #pragma unroll
    for (int t = 0; t < 16; t++)
        #pragma unroll
        for (int q = 0; q < 4; q++) acc[t][q] = 0.f;

    #pragma unroll
    for (int kk = 0; kk < 256; kk += 16) {
        uint32_t a0 = *(const uint32_t*)&As[(m0 + r) * KP + kk + c2];
        uint32_t a1 = *(const uint32_t*)&As[(m0 + r + 8) * KP + kk + c2];
        uint32_t a2 = *(const uint32_t*)&As[(m0 + r) * KP + kk + 8 + c2];
        uint32_t a3 = *(const uint32_t*)&As[(m0 + r + 8) * KP + kk + 8 + c2];
        #pragma unroll
        for (int nt = 0; nt < 16; nt++) {
            uint32_t b0 = *(const uint32_t*)&Bs[(nt * 8 + r) * KP + kk + c2];
            uint32_t b1r = *(const uint32_t*)&Bs[(nt * 8 + r) * KP + kk + 8 + c2];
            mma16816(acc[nt], a0, a1, a2, a3, b0, b1r);
        }
    }

    const int row0 = block_row + m0 + r;
    #pragma unroll
    for (int nt = 0; nt < 16; nt++) {
        int col = nt * 8 + c2;
        float bx = bias_s[col], by = bias_s[col + 1];
        if (row0 < n) {
            float2 o = make_float2(fmaxf(acc[nt][0] + bx, 0.f),
                                   fmaxf(acc[nt][1] + by, 0.f));
            *(float2*)(out + (size_t)row0 * DIM + col) = o;
        }
        if (row0 + 8 < n) {
            float2 o = make_float2(fmaxf(acc[nt][2] + bx, 0.f),
                                   fmaxf(acc[nt][3] + by, 0.f));
            *(float2*)(out + (size_t)(row0 + 8) * DIM + col) = o;
        }
    }
}

static const int SMEM_G1 = (128 * 136 * 2) * 2 + 512;
static const int SMEM_G2 = (128 * 264 * 2) * 2 + 512;

// ---------------- host launcher ----------------
extern "C" void kernel_launch(void* const* d_in, const int* in_sizes, int n_in,
                              void* d_out, int out_size) {
    const float* feat = (const float*)d_in[0];
    const void*  ei   = d_in[1];
    const float* W1   = (const float*)d_in[2];
    const float* b1   = (const float*)d_in[3];
    const float* Wl   = (const float*)d_in[4];
    const float* bl   = (const float*)d_in[5];
    const float* Wr   = (const float*)d_in[6];
    float* out = (float*)d_out;

    const int n = in_sizes[0] / DIM;
    const long long E = (long long)in_sizes[1] / 2;

    static bool attr_done = false;
    if (!attr_done) {
        cudaFuncSetAttribute(mma_gemm1, cudaFuncAttributeMaxDynamicSharedMemorySize, SMEM_G1);
        cudaFuncSetAttribute(mma_gemm2, cudaFuncAttributeMaxDynamicSharedMemorySize, SMEM_G2);
        attr_done = true;
    }

    const int eb = (int)((E + 255) / 256);
    const int nb = (n + 255) / 256;
    const int wb = (n + 7) / 8;
    const int mb = (n + 127) / 128;
    const int cb = (n * 32 + 255) / 256;

    detect_kernel<<<1, 256>>>((const int*)ei, 2 * E);
    conv_kernel<<<cb, 256>>>(feat, out, n);
    count_deg_kernel<<<eb, 256>>>(ei, E);
    precomp_partial_kernel<<<nb, 256>>>(n);
    scan_part_kernel<<<1, 512>>>(nb, n);
    rowptr_kernel<<<nb, 256>>>(n);
    fill_kernel<<<eb, 256>>>(ei, E);
    agg1_kernel<<<wb, 256>>>(out, n);
    mma_gemm1<<<mb, 256, SMEM_G1>>>(W1, b1, out, n);
    sgather_kernel<<<wb, 256>>>(out, n);
    mma_gemm2<<<mb, 256, SMEM_G2>>>(Wl, bl, Wr, out, n);
}

// round 13
// speedup vs baseline: 1.1884x; 1.1197x over previous
#include <cuda_runtime.h>
#include <cuda_fp16.h>
#include <cstdint>

#define MAX_N 100352
#define MAX_E 1700000
#define MAX_PART 512
#define DIM 128

// ---------------- small device-global scratch (~8.6 MB) ----------------
__device__ int    g_deg[MAX_N];
__device__ float  g_dinv[MAX_N];
__device__ float  g_invcnt[MAX_N];
__device__ int    g_row[MAX_N + 1];
__device__ int    g_col[MAX_E];
__device__ int    g_part[MAX_PART];
__device__ int    g_idx64;
__device__ __half g_W16[3 * 128 * 128];   // W1 | Wl | Wr as fp16

// ---------------- fused prep: detect + feat->fp16 + weights->fp16 + deg=0 ----------------
__global__ __launch_bounds__(256) void prep_kernel(
    const int* __restrict__ ei32, long long words,
    const float* __restrict__ feat,
    const float* __restrict__ W1, const float* __restrict__ Wl,
    const float* __restrict__ Wr,
    float* __restrict__ out, int n)
{
    // detection (block 0): int64 ids < 2^31 -> every odd 32-bit word is 0
    if (blockIdx.x == 0) {
        __shared__ int s;
        if (threadIdx.x == 0) s = 1;
        __syncthreads();
        long long limit = words < 8192 ? words : 8192;
        for (long long j = 1 + 2LL * threadIdx.x; j < limit; j += 512)
            if (ei32[j] != 0) s = 0;
        __syncthreads();
        if (threadIdx.x == 0 && words > 0) g_idx64 = s;
    }
    const int gtid = blockIdx.x * 256 + threadIdx.x;
    const int gstride = gridDim.x * 256;
    // weights: 3 * 4096 float4 groups
    for (int idx = gtid; idx < 3 * 4096; idx += gstride) {
        const float* src = (idx < 4096) ? W1 : (idx < 8192) ? Wl : Wr;
        int off = idx & 4095;
        float4 w = ((const float4*)src)[off];
        __half2 h0 = __floats2half2_rn(w.x, w.y);
        __half2 h1 = __floats2half2_rn(w.z, w.w);
        __half2* dst = (__half2*)&g_W16[(size_t)idx * 4];
        dst[0] = h0; dst[1] = h1;
    }
    // feat fp32 -> fp16 into slot high half of d_out
    const int total = n * 32;
    for (int idx = gtid; idx < total; idx += gstride) {
        int row = idx >> 5, q = idx & 31;
        float4 v = ((const float4*)feat)[idx];
        __half2* dst = (__half2*)((__half*)(out + (size_t)row * DIM + 64)) + q * 2;
        dst[0] = __floats2half2_rn(v.x, v.y);
        dst[1] = __floats2half2_rn(v.z, v.w);
    }
    for (int i = gtid; i < n; i += gstride) g_deg[i] = 0;
}

__device__ __forceinline__ void load_edge(const void* ei, long long E, long long e,
                                          int& src, int& dst) {
    if (g_idx64) {
        const long long* p = (const long long*)ei;
        src = (int)p[e]; dst = (int)p[E + e];
    } else {
        const int* p = (const int*)ei;
        src = p[e]; dst = p[E + e];
    }
}

// ---------------- degree count ----------------
__global__ void count_deg_kernel(const void* ei, long long E) {
    long long e = (long long)blockIdx.x * blockDim.x + threadIdx.x;
    if (e < E) {
        int s, d; load_edge(ei, E, e, s, d);
        atomicAdd(&g_deg[d], 1);
    }
}

// ---------------- precompute norms + scan partials (fused) ----------------
__global__ __launch_bounds__(256) void precomp_partial_kernel(int n) {
    __shared__ int red[256];
    int i = blockIdx.x * 256 + threadIdx.x;
    int d = 0;
    if (i < n) {
        d = g_deg[i];
        g_dinv[i]   = rsqrtf((float)d + 1.0f);
        g_invcnt[i] = 1.0f / (float)(d > 0 ? d : 1);
    }
    red[threadIdx.x] = d;
    __syncthreads();
    for (int s = 128; s > 0; s >>= 1) {
        if (threadIdx.x < s) red[threadIdx.x] += red[threadIdx.x + s];
        __syncthreads();
    }
    if (threadIdx.x == 0) g_part[blockIdx.x] = red[0];
}

__global__ __launch_bounds__(512) void scan_part_kernel(int nb, int n) {
    __shared__ int sp[512];
    int t = threadIdx.x;
    int v = (t < nb) ? g_part[t] : 0;
    sp[t] = v;
    __syncthreads();
    for (int d = 1; d < 512; d <<= 1) {
        int u = (t >= d) ? sp[t - d] : 0;
        __syncthreads();
        sp[t] += u;
        __syncthreads();
    }
    if (t < nb) g_part[t] = sp[t] - v;
    if (t == 511) g_row[n] = sp[511];
}

__global__ __launch_bounds__(256) void rowptr_kernel(int n) {
    __shared__ int sp[256];
    int t = threadIdx.x;
    int i = blockIdx.x * 256 + t;
    int v = (i < n) ? g_deg[i] : 0;
    sp[t] = v;
    __syncthreads();
    for (int d = 1; d < 256; d <<= 1) {
        int u = (t >= d) ? sp[t - d] : 0;
        __syncthreads();
        sp[t] += u;
        __syncthreads();
    }
    int excl = sp[t] - v + g_part[blockIdx.x];
    if (i < n) { g_row[i] = excl; g_deg[i] = excl; }
}

__global__ void fill_kernel(const void* ei, long long E) {
    long long e = (long long)blockIdx.x * blockDim.x + threadIdx.x;
    if (e < E) {
        int s, d; load_edge(ei, E, e, s, d);
        int pos = atomicAdd(&g_deg[d], 1);
        g_col[pos] = s;
    }
}

// ---------------- L1 aggregate: half-warp-per-neighbor, 2 rows in flight ----------------
__global__ __launch_bounds__(256) void agg1_kernel(float* __restrict__ out, int n) {
    int node = blockIdx.x * 8 + (threadIdx.x >> 5);
    if (node >= n) return;
    const int lane = threadIdx.x & 31;
    const int half = lane >> 4, sub = lane & 15;
    const float di = g_dinv[node];

    float acc[8];
    {
        uint4 v = *(const uint4*)((const __half*)(out + (size_t)node * DIM + 64) + sub * 8);
        const __half2* h = (const __half2*)&v;
        float c0 = (half == 0) ? di * di : 0.f;
        #pragma unroll
        for (int q = 0; q < 4; q++) {
            float2 f = __half22float2(h[q]);
            acc[2 * q] = c0 * f.x; acc[2 * q + 1] = c0 * f.y;
        }
    }

    const int pend = g_row[node + 1];
    int p = g_row[node];
    for (; p + 4 <= pend; p += 4) {
        int ja = g_col[p + half], jb = g_col[p + 2 + half];
        float ca = di * g_dinv[ja], cb = di * g_dinv[jb];
        uint4 va = *(const uint4*)((const __half*)(out + (size_t)ja * DIM + 64) + sub * 8);
        uint4 vb = *(const uint4*)((const __half*)(out + (size_t)jb * DIM + 64) + sub * 8);
        const __half2* ha = (const __half2*)&va;
        const __half2* hb = (const __half2*)&vb;
        #pragma unroll
        for (int q = 0; q < 4; q++) {
            float2 fa = __half22float2(ha[q]);
            float2 fb = __half22float2(hb[q]);
            acc[2 * q]     += ca * fa.x + cb * fb.x;
            acc[2 * q + 1] += ca * fa.y + cb * fb.y;
        }
    }
    for (; p + 2 <= pend; p += 2) {
        int j = g_col[p + half];
        float c = di * g_dinv[j];
        uint4 v = *(const uint4*)((const __half*)(out + (size_t)j * DIM + 64) + sub * 8);
        const __half2* h = (const __half2*)&v;
        #pragma unroll
        for (int q = 0; q < 4; q++) {
            float2 f = __half22float2(h[q]);
            acc[2 * q] += c * f.x; acc[2 * q + 1] += c * f.y;
        }
    }
    if (p + half < pend) {
        int j = g_col[p + half];
        float c = di * g_dinv[j];
        uint4 v = *(const uint4*)((const __half*)(out + (size_t)j * DIM + 64) + sub * 8);
        const __half2* h = (const __half2*)&v;
        #pragma unroll
        for (int q = 0; q < 4; q++) {
            float2 f = __half22float2(h[q]);
            acc[2 * q] += c * f.x; acc[2 * q + 1] += c * f.y;
        }
    }

    #pragma unroll
    for (int q = 0; q < 8; q++)
        acc[q] += __shfl_xor_sync(0xffffffffu, acc[q], 16);

    if (half == 0) {
        __half2 hh[4];
        #pragma unroll
        for (int q = 0; q < 4; q++) hh[q] = __floats2half2_rn(acc[2 * q], acc[2 * q + 1]);
        *(uint4*)((__half*)(out + (size_t)node * DIM) + sub * 8) = *(const uint4*)hh;
    }
}

// ---------------- tensor-core mma helper ----------------
__device__ __forceinline__ void mma16816(float* c, uint32_t a0, uint32_t a1,
                                         uint32_t a2, uint32_t a3,
                                         uint32_t b0, uint32_t b1) {
    asm volatile(
        "mma.sync.aligned.m16n8k16.row.col.f32.f16.f16.f32 "
        "{%0,%1,%2,%3}, {%4,%5,%6,%7}, {%8,%9}, {%0,%1,%2,%3};"
        : "+f"(c[0]), "+f"(c[1]), "+f"(c[2]), "+f"(c[3])
        : "r"(a0), "r"(a1), "r"(a2), "r"(a3), "r"(b0), "r"(b1));
}

// ---------------- GEMM1 (tc): X = relu(agg@W1^T + b1) -> fp16 slot low ----------------
__global__ __launch_bounds__(256) void mma_gemm1(
    const float* __restrict__ b1, float* __restrict__ out, int n)
{
    const int KP = 136;
    extern __shared__ __half sh[];
    __half* As = sh;
    __half* Bs = sh + 128 * KP;
    float* bias_s = (float*)(Bs + 128 * KP);
    const int tid = threadIdx.x;
    const int block_row = blockIdx.x * 128;

    for (int i = tid; i < 128 * 16; i += 256) {
        int r = i >> 4, q = i & 15;
        *(uint4*)&Bs[r * KP + q * 8] = *(const uint4*)&g_W16[r * 128 + q * 8];
    }
    for (int i = tid; i < 128 * 16; i += 256) {
        int r = i >> 4, q = i & 15;
        int gr = block_row + r;
        uint4 v = make_uint4(0, 0, 0, 0);
        if (gr < n) v = ((const uint4*)(out + (size_t)gr * DIM))[q];
        *(uint4*)&As[r * KP + q * 8] = v;
    }
    if (tid < 128) bias_s[tid] = b1[tid];
    __syncthreads();

    const int warp = tid >> 5, lane = tid & 31;
    const int m0 = warp * 16;
    const int r = lane >> 2, c2 = (lane & 3) * 2;

    float acc[16][4];
    #pragma unroll
    for (int t = 0; t < 16; t++)
        #pragma unroll
        for (int q = 0; q < 4; q++) acc[t][q] = 0.f;

    #pragma unroll
    for (int kk = 0; kk < 128; kk += 16) {
        uint32_t a0 = *(const uint32_t*)&As[(m0 + r) * KP + kk + c2];
        uint32_t a1 = *(const uint32_t*)&As[(m0 + r + 8) * KP + kk + c2];
        uint32_t a2 = *(const uint32_t*)&As[(m0 + r) * KP + kk + 8 + c2];
        uint32_t a3 = *(const uint32_t*)&As[(m0 + r + 8) * KP + kk + 8 + c2];
        #pragma unroll
        for (int nt = 0; nt < 16; nt++) {
            uint32_t b0 = *(const uint32_t*)&Bs[(nt * 8 + r) * KP + kk + c2];
            uint32_t b1r = *(const uint32_t*)&Bs[(nt * 8 + r) * KP + kk + 8 + c2];
            mma16816(acc[nt], a0, a1, a2, a3, b0, b1r);
        }
    }

    const int row0 = block_row + m0 + r;
    #pragma unroll
    for (int nt = 0; nt < 16; nt++) {
        int col = nt * 8 + c2;
        float bx = bias_s[col], by = bias_s[col + 1];
        if (row0 < n) {
            __half2 h = __floats2half2_rn(fmaxf(acc[nt][0] + bx, 0.f),
                                          fmaxf(acc[nt][1] + by, 0.f));
            *(__half2*)((__half*)(out + (size_t)row0 * DIM) + col) = h;
        }
        if (row0 + 8 < n) {
            __half2 h = __floats2half2_rn(fmaxf(acc[nt][2] + bx, 0.f),
                                          fmaxf(acc[nt][3] + by, 0.f));
            *(__half2*)((__half*)(out + (size_t)(row0 + 8) * DIM) + col) = h;
        }
    }
}

// ---------------- SAGE sum: half-warp gather, 2 rows in flight -> fp16 slot high ----------------
__global__ __launch_bounds__(256) void sgather_kernel(float* __restrict__ out, int n) {
    int node = blockIdx.x * 8 + (threadIdx.x >> 5);
    if (node >= n) return;
    const int lane = threadIdx.x & 31;
    const int half = lane >> 4, sub = lane & 15;

    float acc[8];
    #pragma unroll
    for (int q = 0; q < 8; q++) acc[q] = 0.f;

    const int pend = g_row[node + 1];
    int p = g_row[node];
    for (; p + 4 <= pend; p += 4) {
        int ja = g_col[p + half], jb = g_col[p + 2 + half];
        uint4 va = *(const uint4*)((const __half*)(out + (size_t)ja * DIM) + sub * 8);
        uint4 vb = *(const uint4*)((const __half*)(out + (size_t)jb * DIM) + sub * 8);
        const __half2* ha = (const __half2*)&va;
        const __half2* hb = (const __half2*)&vb;
        #pragma unroll
        for (int q = 0; q < 4; q++) {
            float2 fa = __half22float2(ha[q]);
            float2 fb = __half22float2(hb[q]);
            acc[2 * q]     += fa.x + fb.x;
            acc[2 * q + 1] += fa.y + fb.y;
        }
    }
    for (; p + 2 <= pend; p += 2) {
        int j = g_col[p + half];
        uint4 v = *(const uint4*)((const __half*)(out + (size_t)j * DIM) + sub * 8);
        const __half2* h = (const __half2*)&v;
        #pragma unroll
        for (int q = 0; q < 4; q++) {
            float2 f = __half22float2(h[q]);
            acc[2 * q] += f.x; acc[2 * q + 1] += f.y;
        }
    }
    if (p + half < pend) {
        int j = g_col[p + half];
        uint4 v = *(const uint4*)((const __half*)(out + (size_t)j * DIM) + sub * 8);
        const __half2* h = (const __half2*)&v;
        #pragma unroll
        for (int q = 0; q < 4; q++) {
            float2 f = __half22float2(h[q]);
            acc[2 * q] += f.x; acc[2 * q + 1] += f.y;
        }
    }

    #pragma unroll
    for (int q = 0; q < 8; q++)
        acc[q] += __shfl_xor_sync(0xffffffffu, acc[q], 16);

    if (half == 0) {
        __half2 hh[4];
        #pragma unroll
        for (int q = 0; q < 4; q++) hh[q] = __floats2half2_rn(acc[2 * q], acc[2 * q + 1]);
        *(uint4*)((__half*)(out + (size_t)node * DIM + 64) + sub * 8) = *(const uint4*)hh;
    }
}

// ---------------- GEMM2 (tc): out = relu([S*invcnt | X] @ [Wl|Wr]^T + bl) ----------------
__global__ __launch_bounds__(256) void mma_gemm2(
    const float* __restrict__ bl, float* __restrict__ out, int n)
{
    const int KP = 264;
    extern __shared__ __half sh[];
    __half* As = sh;
    __half* Bs = sh + 128 * KP;
    float* bias_s = (float*)(Bs + 128 * KP);
    const int tid = threadIdx.x;
    const int block_row = blockIdx.x * 128;

    // B: cols [0:128)=Wl (g_W16 + 16384), [128:256)=Wr (g_W16 + 32768)
    for (int i = tid; i < 128 * 16; i += 256) {
        int r = i >> 4, q = i & 15;
        *(uint4*)&Bs[r * KP + q * 8] = *(const uint4*)&g_W16[16384 + r * 128 + q * 8];
        *(uint4*)&Bs[r * KP + 128 + q * 8] = *(const uint4*)&g_W16[32768 + r * 128 + q * 8];
    }
    for (int i = tid; i < 128 * 64; i += 256) {
        int row = i >> 6, q = i & 63;
        int gr = block_row + row;
        __half2 xh = __float2half2_rn(0.f), shv = __float2half2_rn(0.f);
        if (gr < n) {
            const __half2* slot = (const __half2*)(out + (size_t)gr * DIM);
            xh = slot[q];
            __half2 sr = slot[64 + q];
            float ic = g_invcnt[gr];
            float2 sf = __half22float2(sr);
            shv = __floats2half2_rn(sf.x * ic, sf.y * ic);
        }
        ((__half2*)&As[row * KP])[q] = shv;
        ((__half2*)&As[row * KP + 128])[q] = xh;
    }
    if (tid < 128) bias_s[tid] = bl[tid];
    __syncthreads();

    const int warp = tid >> 5, lane = tid & 31;
    const int m0 = warp * 16;
    const int r = lane >> 2, c2 = (lane & 3) * 2;

    float acc[16][4];
    #pragma unroll
    for (int t = 0; t < 16; t++)
        #pragma unroll
        for (int q = 0; q < 4; q++) acc[t][q] = 0.f;

    #pragma unroll
    for (int kk = 0; kk < 256; kk += 16) {
        uint32_t a0 = *(const uint32_t*)&As[(m0 + r) * KP + kk + c2];
        uint32_t a1 = *(const uint32_t*)&As[(m0 + r + 8) * KP + kk + c2];
        uint32_t a2 = *(const uint32_t*)&As[(m0 + r) * KP + kk + 8 + c2];
        uint32_t a3 = *(const uint32_t*)&As[(m0 + r + 8) * KP + kk + 8 + c2];
        #pragma unroll
        for (int nt = 0; nt < 16; nt++) {
            uint32_t b0 = *(const uint32_t*)&Bs[(nt * 8 + r) * KP + kk + c2];
            uint32_t b1r = *(const uint32_t*)&Bs[(nt * 8 + r) * KP + kk + 8 + c2];
            mma16816(acc[nt], a0, a1, a2, a3, b0, b1r);
        }
    }

    const int row0 = block_row + m0 + r;
    #pragma unroll
    for (int nt = 0; nt < 16; nt++) {
        int col = nt * 8 + c2;
        float bx = bias_s[col], by = bias_s[col + 1];
        if (row0 < n) {
            float2 o = make_float2(fmaxf(acc[nt][0] + bx, 0.f),
                                   fmaxf(acc[nt][1] + by, 0.f));
            *(float2*)(out + (size_t)row0 * DIM + col) = o;
        }
        if (row0 + 8 < n) {
            float2 o = make_float2(fmaxf(acc[nt][2] + bx, 0.f),
                                   fmaxf(acc[nt][3] + by, 0.f));
            *(float2*)(out + (size_t)(row0 + 8) * DIM + col) = o;
        }
    }
}

static const int SMEM_G1 = (128 * 136 * 2) * 2 + 512;
static const int SMEM_G2 = (128 * 264 * 2) * 2 + 512;

// ---------------- host launcher ----------------
extern "C" void kernel_launch(void* const* d_in, const int* in_sizes, int n_in,
                              void* d_out, int out_size) {
    const float* feat = (const float*)d_in[0];
    const void*  ei   = d_in[1];
    const float* W1   = (const float*)d_in[2];
    const float* b1   = (const float*)d_in[3];
    const float* Wl   = (const float*)d_in[4];
    const float* bl   = (const float*)d_in[5];
    const float* Wr   = (const float*)d_in[6];
    float* out = (float*)d_out;

    const int n = in_sizes[0] / DIM;
    const long long E = (long long)in_sizes[1] / 2;

    static bool attr_done = false;
    if (!attr_done) {
        cudaFuncSetAttribute(mma_gemm1, cudaFuncAttributeMaxDynamicSharedMemorySize, SMEM_G1);
        cudaFuncSetAttribute(mma_gemm2, cudaFuncAttributeMaxDynamicSharedMemorySize, SMEM_G2);
        attr_done = true;
    }

    const int eb = (int)((E + 255) / 256);
    const int nb = (n + 255) / 256;
    const int wb = (n + 7) / 8;
    const int mb = (n + 127) / 128;
    const int pb = (n * 32 + 255) / 256;

    prep_kernel<<<pb, 256>>>((const int*)ei, 2 * E, feat, W1, Wl, Wr, out, n);
    count_deg_kernel<<<eb, 256>>>(ei, E);
    precomp_partial_kernel<<<nb, 256>>>(n);
    scan_part_kernel<<<1, 512>>>(nb, n);
    rowptr_kernel<<<nb, 256>>>(n);
    fill_kernel<<<eb, 256>>>(ei, E);
    agg1_kernel<<<wb, 256>>>(out, n);
    mma_gemm1<<<mb, 256, SMEM_G1>>>(b1, out, n);
    sgather_kernel<<<wb, 256>>>(out, n);
    mma_gemm2<<<mb, 256, SMEM_G2>>>(bl, out, n);
}